// round 17
// baseline (speedup 1.0000x reference)
#include <cuda_runtime.h>
#include <cuda_fp16.h>
#include <cstdint>

// Problem constants
#define HW   4096
#define CCH  64
#define CQD  8
#define NBAT 4
#define NSPL 4          // denom j-split
#define NS   8          // attn key-split
#define NC   (HW / (NS * 128))   // chunks per attn block = 4
#define PSZ  (NBAT * CCH * HW)
#define L2E  1.4426950408889634f

// Scratch (device globals — no allocation allowed)
__device__ __half g_Qh[NBAT * HW * CQD];      // [b][m][8] fp16, pre-scaled by log2(e)
__device__ __half g_Kh[NBAT * HW * CQD];      // [b][n][8] fp16
__device__ __half g_Vh[NBAT * CCH * HW];      // [b][c][m] fp16 (raw; normalization via bias)
__device__ float  g_dpart[NSPL * NBAT * HW];  // per-split softmax denominators
__device__ __half g_bias[NBAT * HW];          // 12 - log2(denom[m]), f16
__device__ __half g_Dph[NS * PSZ];            // attn split partials [s][b][c][n], raw f16 accums

// ---------------------------------------------------------------------------
// helpers
// ---------------------------------------------------------------------------
__device__ __forceinline__ uint32_t smem_u32(const void* p) {
    uint32_t a;
    asm("{ .reg .u64 t; cvta.to.shared.u64 t, %1; cvt.u32.u64 %0, t; }" : "=r"(a) : "l"(p));
    return a;
}
__device__ __forceinline__ void ldsm2(uint32_t* r, uint32_t addr) {
    asm volatile("ldmatrix.sync.aligned.m8n8.x2.shared.b16 {%0,%1}, [%2];"
                 : "=r"(r[0]), "=r"(r[1]) : "r"(addr));
}
__device__ __forceinline__ void ldsm4(uint32_t* r, uint32_t addr) {
    asm volatile("ldmatrix.sync.aligned.m8n8.x4.shared.b16 {%0,%1,%2,%3}, [%4];"
                 : "=r"(r[0]), "=r"(r[1]), "=r"(r[2]), "=r"(r[3]) : "r"(addr));
}
__device__ __forceinline__ void ldsm4t(uint32_t* r, uint32_t addr) {
    asm volatile("ldmatrix.sync.aligned.m8n8.x4.trans.shared.b16 {%0,%1,%2,%3}, [%4];"
                 : "=r"(r[0]), "=r"(r[1]), "=r"(r[2]), "=r"(r[3]) : "r"(addr));
}
// scores, f16 accumulate, zero C init (denom)
__device__ __forceinline__ void mma8h(uint32_t& c0, uint32_t& c1,
                                      const uint32_t* a, uint32_t b) {
    asm volatile("mma.sync.aligned.m16n8k8.row.col.f16.f16.f16.f16 "
                 "{%0,%1}, {%2,%3}, {%4}, {%5,%6};"
                 : "=r"(c0), "=r"(c1)
                 : "r"(a[0]), "r"(a[1]), "r"(b), "r"(0u), "r"(0u));
}
// scores with per-column bias C init (attn: softmax normalization folded in)
__device__ __forceinline__ void mma8hb(uint32_t& c0, uint32_t& c1,
                                       const uint32_t* a, uint32_t b, uint32_t bias) {
    asm volatile("mma.sync.aligned.m16n8k8.row.col.f16.f16.f16.f16 "
                 "{%0,%1}, {%2,%3}, {%4}, {%5,%6};"
                 : "=r"(c0), "=r"(c1)
                 : "r"(a[0]), "r"(a[1]), "r"(b), "r"(bias), "r"(bias));
}
// P@V, f16 accumulate
__device__ __forceinline__ void mma16h(uint32_t* d, const uint32_t* a,
                                       uint32_t b0, uint32_t b1) {
    asm volatile("mma.sync.aligned.m16n8k16.row.col.f16.f16.f16.f16 "
                 "{%0,%1}, {%2,%3,%4,%5}, {%6,%7}, {%0,%1};"
                 : "+r"(d[0]), "+r"(d[1])
                 : "r"(a[0]), "r"(a[1]), "r"(a[2]), "r"(a[3]), "r"(b0), "r"(b1));
}
// qkv GEMM keeps f32 accumulate
__device__ __forceinline__ void mma16(float* d, const uint32_t* a,
                                      uint32_t b0, uint32_t b1) {
    asm volatile("mma.sync.aligned.m16n8k16.row.col.f32.f16.f16.f32 "
                 "{%0,%1,%2,%3}, {%4,%5,%6,%7}, {%8,%9}, {%0,%1,%2,%3};"
                 : "+f"(d[0]), "+f"(d[1]), "+f"(d[2]), "+f"(d[3])
                 : "r"(a[0]), "r"(a[1]), "r"(a[2]), "r"(a[3]), "r"(b0), "r"(b1));
}
__device__ __forceinline__ uint32_t cvt_h2(float lo, float hi) {
    uint32_t r;
    asm("cvt.rn.f16x2.f32 %0, %1, %2;" : "=r"(r) : "f"(hi), "f"(lo));
    return r;
}
__device__ __forceinline__ uint32_t h2ex2(uint32_t a) {
    uint32_t r;
    asm("ex2.approx.f16x2 %0, %1;" : "=r"(r) : "r"(a));
    return r;
}
__device__ __forceinline__ uint32_t hadd2_(uint32_t a, uint32_t b) {
    uint32_t r;
    asm("add.f16x2 %0, %1, %2;" : "=r"(r) : "r"(a), "r"(b));
    return r;
}
__device__ __forceinline__ void cp16(uint32_t smem, const void* g) {
    asm volatile("cp.async.cg.shared.global [%0], [%1], 16;" :: "r"(smem), "l"(g));
}
#define CP_COMMIT() asm volatile("cp.async.commit_group;" ::: "memory")
#define CP_WAIT(n)  asm volatile("cp.async.wait_group %0;" :: "n"(n) : "memory")

// ---------------------------------------------------------------------------
// Kernel 1: QKV projections as a tensor-core GEMM (f32 acc).
// ---------------------------------------------------------------------------
#define XSTR  272
#define WSTR  144
#define SM_X  0
#define SM_W  17408
#define SM_BI 41472
#define SDSTR 81

__global__ __launch_bounds__(256) void qkv_kernel(
    const float* __restrict__ x,
    const float* __restrict__ Wq, const float* __restrict__ bq,
    const float* __restrict__ Wk, const float* __restrict__ bk,
    const float* __restrict__ Wv, const float* __restrict__ bv)
{
    __shared__ __align__(16) uint8_t sm[41792];
    const uint32_t smb = smem_u32(sm);

    const int t = threadIdx.x, w = t >> 5, l = t & 31;
    const int b = blockIdx.y;
    const int n0 = blockIdx.x * 128;

    float* bs = (float*)(sm + SM_BI);
    if (t < 80) {
        float v;
        if (t < 64)      v = bv[t];
        else if (t < 72) v = bq[t - 64] * L2E;
        else             v = bk[t - 72];
        bs[t] = v;
    }
#pragma unroll
    for (int idx = t; idx < 80 * 32; idx += 256) {
        const int o = idx >> 5, p = idx & 31;
        float lo, hi;
        if (o < 64)      { lo = Wv[o * 64 + 2 * p];          hi = Wv[o * 64 + 2 * p + 1]; }
        else if (o < 72) { lo = Wq[(o - 64) * 64 + 2 * p] * L2E;
                           hi = Wq[(o - 64) * 64 + 2 * p + 1] * L2E; }
        else             { lo = Wk[(o - 72) * 64 + 2 * p];   hi = Wk[(o - 72) * 64 + 2 * p + 1]; }
        *(uint32_t*)(sm + SM_W + o * WSTR + p * 4) = cvt_h2(lo, hi);
    }
    const float* xb = x + (size_t)b * CCH * HW + n0;
#pragma unroll
    for (int idx = t; idx < 64 * 64; idx += 256) {
        const int c = idx >> 6, p = idx & 63;
        float2 v = *(const float2*)(xb + (size_t)c * HW + 2 * p);
        *(uint32_t*)(sm + SM_X + c * XSTR + p * 4) = cvt_h2(v.x, v.y);
    }
    __syncthreads();

    float dacc[10][4];
#pragma unroll
    for (int ct = 0; ct < 10; ct++)
#pragma unroll
        for (int i = 0; i < 4; i++) dacc[ct][i] = 0.0f;

    const int nb = 16 * w;
#pragma unroll
    for (int ks = 0; ks < 4; ks++) {
        uint32_t a[4];
        ldsm4t(a, smb + SM_X
                  + ((l & 7) + ((l >> 4) & 1) * 8 + 16 * ks) * XSTR
                  + (nb + ((l >> 3) & 1) * 8) * 2);
#pragma unroll
        for (int ot = 0; ot < 5; ot++) {
            uint32_t bb[4];
            ldsm4(bb, smb + SM_W + (ot * 16 + ((l >> 4) << 3) + (l & 7)) * WSTR
                      + ks * 32 + ((l >> 3) & 1) * 16);
            mma16(dacc[2 * ot],     a, bb[0], bb[1]);
            mma16(dacc[2 * ot + 1], a, bb[2], bb[3]);
        }
    }

    __syncthreads();
    float* sD = (float*)sm;
    const int r = l >> 2, q = l & 3;
#pragma unroll
    for (int ct = 0; ct < 10; ct++) {
        const int c = ct * 8 + 2 * q;
        sD[(nb + r) * SDSTR + c]         = dacc[ct][0];
        sD[(nb + r) * SDSTR + c + 1]     = dacc[ct][1];
        sD[(nb + r + 8) * SDSTR + c]     = dacc[ct][2];
        sD[(nb + r + 8) * SDSTR + c + 1] = dacc[ct][3];
    }
    __syncthreads();

#pragma unroll
    for (int idx = t; idx < 64 * 64; idx += 256) {
        const int c = idx >> 6, p = idx & 63;
        const float bvv = bs[c];
        const float lo = sD[(2 * p) * SDSTR + c] + bvv;
        const float hi = sD[(2 * p + 1) * SDSTR + c] + bvv;
        *(uint32_t*)(g_Vh + ((size_t)b * CCH + c) * HW + n0 + 2 * p) = cvt_h2(lo, hi);
    }
    {
        const int n = t & 127;
        const int base = (t < 128) ? 64 : 72;
        __half* dst = (t < 128) ? g_Qh : g_Kh;
        uint32_t u[4];
#pragma unroll
        for (int jj = 0; jj < 4; jj++)
            u[jj] = cvt_h2(sD[n * SDSTR + base + 2 * jj] + bs[base + 2 * jj],
                           sD[n * SDSTR + base + 2 * jj + 1] + bs[base + 2 * jj + 1]);
        *(uint4*)(dst + ((size_t)b * HW + n0 + n) * CQD) = make_uint4(u[0], u[1], u[2], u[3]);
    }
}

// ---------------------------------------------------------------------------
// Kernel 2: softmax denominators — f16-acc MMA scores + f16x2 ex2,
//   K chunks double-buffered via cp.async.
// ---------------------------------------------------------------------------
__global__ __launch_bounds__(256) void denom_kernel()
{
    __shared__ __align__(16) uint8_t sm[6144];
    const uint32_t smb = smem_u32(sm);

    const int t = threadIdx.x, w = t >> 5, l = t & 31;
    const int b = blockIdx.z, s = blockIdx.y;
    const int mbase = blockIdx.x * 128;

    const uint4* Qg = (const uint4*)(g_Qh + (size_t)b * HW * CQD);
    const uint4* Kg = (const uint4*)(g_Kh + (size_t)b * HW * CQD);

    if (t < 128) *(uint4*)(sm + t * 16) = Qg[mbase + t];

    auto stageK = [&](int buf, int nn0) {
        if (t < 128) cp16(smb + (buf ? 4096 : 2048) + t * 16, Kg + nn0 + t);
    };
    const int nbase = s * (HW / NSPL);
    stageK(0, nbase);
    CP_COMMIT();

    __syncthreads();
    uint32_t qa[2];
    ldsm2(qa, smb + (16 * w + (l & 15)) * 16);

    float rs0 = 0.0f, rs1 = 0.0f;
    const int NCH = (HW / NSPL) / 128;           // 8
    for (int ch = 0; ch < NCH; ch++) {
        const int buf = ch & 1;
        if (ch + 1 < NCH) {
            stageK(buf ^ 1, nbase + (ch + 1) * 128);
            CP_COMMIT();
            CP_WAIT(1);
        } else {
            CP_WAIT(0);
        }
        __syncthreads();
        const uint32_t kbase = smb + (buf ? 4096 : 2048);
        uint32_t kb[16];
        ldsm4(kb + 0,  kbase + l * 16);
        ldsm4(kb + 4,  kbase + (32 + l) * 16);
        ldsm4(kb + 8,  kbase + (64 + l) * 16);
        ldsm4(kb + 12, kbase + (96 + l) * 16);
        uint32_t a0 = 0u, a1 = 0u;
#pragma unroll
        for (int jj = 0; jj < 16; jj++) {
            uint32_t c0, c1;
            mma8h(c0, c1, qa, kb[jj]);
            a0 = hadd2_(a0, h2ex2(c0));
            a1 = hadd2_(a1, h2ex2(c1));
        }
        float2 f0 = __half22float2(*reinterpret_cast<__half2*>(&a0));
        float2 f1 = __half22float2(*reinterpret_cast<__half2*>(&a1));
        rs0 += f0.x + f0.y;
        rs1 += f1.x + f1.y;
        __syncthreads();
    }
    rs0 += __shfl_xor_sync(0xFFFFFFFFu, rs0, 1);
    rs0 += __shfl_xor_sync(0xFFFFFFFFu, rs0, 2);
    rs1 += __shfl_xor_sync(0xFFFFFFFFu, rs1, 1);
    rs1 += __shfl_xor_sync(0xFFFFFFFFu, rs1, 2);
    if ((l & 3) == 0) {
        const int r = 16 * w + (l >> 2);
        float* dst = g_dpart + ((size_t)s * NBAT + b) * HW + mbase;
        dst[r]     = rs0;
        dst[r + 8] = rs1;
    }
}

// ---------------------------------------------------------------------------
// Kernel 3: finalize — bias[m] = 12 - log2(denom[m])  (f16)
// ---------------------------------------------------------------------------
__global__ __launch_bounds__(256) void finalize_kernel()
{
    const int i = blockIdx.x * 256 + threadIdx.x;   // over NBAT*HW
    float d = g_dpart[i]
            + g_dpart[(size_t)NBAT * HW + i]
            + g_dpart[(size_t)2 * NBAT * HW + i]
            + g_dpart[(size_t)3 * NBAT * HW + i];
    g_bias[i] = __float2half(12.0f - __log2f(d));
}

// ---------------------------------------------------------------------------
// Kernel 4: attention aggregation — 4 warps x 32 pixel rows, NS=8 splits,
//   6 blocks/SM (38 KB smem, ~70 regs).  Per chunk: scores(half) -> PV(half)
//   twice, halving pa live range.  V swizzled 256B rows; K region reused
//   as bias ring after K is consumed.
// SMEM: V0 @0 (16K) | V1 @16K | Q0 @32768 | Q1 @34816 | K/bias @36864
// ---------------------------------------------------------------------------
#define SM_V0 0
#define SM_V1 16384
#define SM_Q0 32768
#define SM_Q1 34816
#define SM_KB 36864
#define SMA_BYTES 38912
#define OSTR  65

__global__ __launch_bounds__(128, 6) void attn_kernel()
{
    __shared__ __align__(16) uint8_t sm[SMA_BYTES];
    const uint32_t smb = smem_u32(sm);

    const int t = threadIdx.x, w = t >> 5, l = t & 31;
    const int s = blockIdx.y;
    const int b = blockIdx.z;
    const int n0 = blockIdx.x * 128;

    const uint4* Kg = (const uint4*)(g_Kh + (size_t)b * HW * CQD);
    const uint4* Qg = (const uint4*)(g_Qh + (size_t)b * HW * CQD);
    const uint4* Vg = (const uint4*)(g_Vh + (size_t)b * CCH * HW);
    const __half* Bg = g_bias + (size_t)b * HW;

    // K tile through the K/bias region; consumed into registers first
    *(uint4*)(sm + SM_KB + t * 16) = Kg[n0 + t];
    __syncthreads();
    uint32_t kaA[2], kaB[2];
    ldsm2(kaA, smb + SM_KB + (32 * w + (l & 15)) * 16);
    ldsm2(kaB, smb + SM_KB + (32 * w + 16 + (l & 15)) * 16);
    __syncthreads();                       // K consumed; region free for bias

    auto stage = [&](int buf, int m0) {
        const uint32_t vbase = smb + (buf ? SM_V1 : SM_V0);
#pragma unroll
        for (int jj = 0; jj < 8; jj++) {
            int i = t + jj * 128;
            int row = i >> 4, c16 = i & 15;
            cp16(vbase + row * 256 + ((c16 ^ (row & 7)) << 4),
                 Vg + (size_t)row * (HW / 8) + (m0 >> 3) + c16);
        }
        cp16(smb + (buf ? SM_Q1 : SM_Q0) + t * 16, Qg + m0 + t);
        if (t < 16) cp16(smb + SM_KB + (buf ? 256 : 0) + t * 16, Bg + m0 + t * 8);
    };

    stage(0, s * NC * 128);
    CP_COMMIT();

    uint32_t daccA[8][2], daccB[8][2];
#pragma unroll
    for (int ct = 0; ct < 8; ct++) {
        daccA[ct][0] = daccA[ct][1] = 0u;
        daccB[ct][0] = daccB[ct][1] = 0u;
    }

    for (int chunk = 0; chunk < NC; chunk++) {
        const int buf = chunk & 1;
        if (chunk + 1 < NC) {
            stage(buf ^ 1, (s * NC + chunk + 1) * 128);
            CP_COMMIT();
            CP_WAIT(1);
        } else {
            CP_WAIT(0);
        }
        __syncthreads();

        const uint32_t vbase = smb + (buf ? SM_V1 : SM_V0);
        const uint32_t qbase = smb + (buf ? SM_Q1 : SM_Q0);
        const uint8_t* bptr = sm + SM_KB + (buf ? 256 : 0);

#pragma unroll
        for (int half = 0; half < 2; half++) {
            // ---- scores for this half (keys m = 64*half .. 64*half+63) ----
            uint32_t qb[8];
            ldsm4(qb + 0, qbase + (64 * half + l) * 16);
            ldsm4(qb + 4, qbase + (64 * half + 32 + l) * 16);
            uint32_t paA[4][4], paB[4][4];
#pragma unroll
            for (int jj = 0; jj < 8; jj++) {
                const int jt = 8 * half + jj;
                const uint32_t bias = *(const uint32_t*)(bptr + (jt * 4 + (l & 3)) * 4);
                uint32_t c0, c1;
                mma8hb(c0, c1, kaA, qb[jj], bias);
                paA[jj >> 1][(jj & 1) * 2]     = h2ex2(c0);
                paA[jj >> 1][(jj & 1) * 2 + 1] = h2ex2(c1);
                mma8hb(c0, c1, kaB, qb[jj], bias);
                paB[jj >> 1][(jj & 1) * 2]     = h2ex2(c0);
                paB[jj >> 1][(jj & 1) * 2 + 1] = h2ex2(c1);
            }

            // ---- PV for this half (kk = 4*half + kkl) ----
#pragma unroll
            for (int kkl = 0; kkl < 4; kkl++) {
                const int kk = half * 4 + kkl;
#pragma unroll
                for (int cp = 0; cp < 4; cp++) {
                    const int row = cp * 16 + ((l >> 4) << 3) + (l & 7);
                    const int c16 = kk * 2 + ((l >> 3) & 1);
                    uint32_t bb[4];
                    ldsm4(bb, vbase + row * 256 + ((c16 ^ (row & 7)) << 4));
                    mma16h(daccA[2 * cp],     paA[kkl], bb[0], bb[1]);
                    mma16h(daccA[2 * cp + 1], paA[kkl], bb[2], bb[3]);
                    mma16h(daccB[2 * cp],     paB[kkl], bb[0], bb[1]);
                    mma16h(daccB[2 * cp + 1], paB[kkl], bb[2], bb[3]);
                }
            }
        }
        __syncthreads();
    }

    // ---- f16 accs -> f32 smem stage (transpose) -> f16 global writes ----
    float* sD = (float*)sm;
    const int r = l >> 2, q = l & 3;
#pragma unroll
    for (int ct = 0; ct < 8; ct++) {
        const int c = ct * 8 + 2 * q;
        float2 lo = __half22float2(*reinterpret_cast<__half2*>(&daccA[ct][0]));
        float2 hi = __half22float2(*reinterpret_cast<__half2*>(&daccA[ct][1]));
        sD[(32 * w + r) * OSTR + c]          = lo.x;
        sD[(32 * w + r) * OSTR + c + 1]      = lo.y;
        sD[(32 * w + r + 8) * OSTR + c]      = hi.x;
        sD[(32 * w + r + 8) * OSTR + c + 1]  = hi.y;
        lo = __half22float2(*reinterpret_cast<__half2*>(&daccB[ct][0]));
        hi = __half22float2(*reinterpret_cast<__half2*>(&daccB[ct][1]));
        sD[(32 * w + 16 + r) * OSTR + c]         = lo.x;
        sD[(32 * w + 16 + r) * OSTR + c + 1]     = lo.y;
        sD[(32 * w + 24 + r) * OSTR + c]         = hi.x;
        sD[(32 * w + 24 + r) * OSTR + c + 1]     = hi.y;
    }
    __syncthreads();

    __half* dst = g_Dph + (size_t)s * PSZ + (size_t)b * CCH * HW;
#pragma unroll
    for (int i = t; i < 64 * 64; i += 128) {
        const int c = i >> 6, p = i & 63;          // p = pixel pair
        const float lo = sD[(2 * p) * OSTR + c];
        const float hi = sD[(2 * p + 1) * OSTR + c];
        *(uint32_t*)(dst + (size_t)c * HW + n0 + 2 * p) = cvt_h2(lo, hi);
    }
}

// ---------------------------------------------------------------------------
// Kernel 5: combine NS f16 split partials + gamma + residual.
// ---------------------------------------------------------------------------
__global__ __launch_bounds__(256) void combine_kernel(
    const float* __restrict__ x,
    const float* __restrict__ gamma,
    float* __restrict__ out)
{
    const size_t i = ((size_t)blockIdx.x * 256 + threadIdx.x) * 8;
    const float gm = gamma[0] * (1.0f / 4096.0f);
    float acc[8];
#pragma unroll
    for (int k = 0; k < 8; k++) acc[k] = 0.0f;
#pragma unroll
    for (int s = 0; s < NS; s++) {
        uint4 v = *(const uint4*)(g_Dph + (size_t)s * PSZ + i);
        float2 f;
        f = __half22float2(*reinterpret_cast<__half2*>(&v.x)); acc[0] += f.x; acc[1] += f.y;
        f = __half22float2(*reinterpret_cast<__half2*>(&v.y)); acc[2] += f.x; acc[3] += f.y;
        f = __half22float2(*reinterpret_cast<__half2*>(&v.z)); acc[4] += f.x; acc[5] += f.y;
        f = __half22float2(*reinterpret_cast<__half2*>(&v.w)); acc[6] += f.x; acc[7] += f.y;
    }
    float4 x0 = *(const float4*)(x + i);
    float4 x1 = *(const float4*)(x + i + 4);
    float4 o0, o1;
    o0.x = gm * acc[0] + x0.x;  o0.y = gm * acc[1] + x0.y;
    o0.z = gm * acc[2] + x0.z;  o0.w = gm * acc[3] + x0.w;
    o1.x = gm * acc[4] + x1.x;  o1.y = gm * acc[5] + x1.y;
    o1.z = gm * acc[6] + x1.z;  o1.w = gm * acc[7] + x1.w;
    *(float4*)(out + i)     = o0;
    *(float4*)(out + i + 4) = o1;
}

// ---------------------------------------------------------------------------
extern "C" void kernel_launch(void* const* d_in, const int* in_sizes, int n_in,
                              void* d_out, int out_size)
{
    const float* x     = (const float*)d_in[0];
    const float* Wq    = (const float*)d_in[1];
    const float* bq    = (const float*)d_in[2];
    const float* Wk    = (const float*)d_in[3];
    const float* bk    = (const float*)d_in[4];
    const float* Wv    = (const float*)d_in[5];
    const float* bv    = (const float*)d_in[6];
    const float* gamma = (const float*)d_in[7];
    float* out = (float*)d_out;

    qkv_kernel<<<dim3(HW / 128, NBAT), 256>>>(x, Wq, bq, Wk, bk, Wv, bv);
    denom_kernel<<<dim3(HW / 128, NSPL, NBAT), 256>>>();
    finalize_kernel<<<(NBAT * HW) / 256, 256>>>();
    attn_kernel<<<dim3(HW / 128, NS, NBAT), 128>>>();
    combine_kernel<<<PSZ / 2048, 256>>>(x, gamma, out);
}